// round 8
// baseline (speedup 1.0000x reference)
#include <cuda_runtime.h>
#include <cstdint>

#define DHN 512
#define BN  64
#define TN  1024
#define NPEER 8
#define NGRP  16

// r vectors per step, never-reused addresses within a launch:
// g_ring[group][slot][batch][d]
__device__ float g_ring[NGRP][TN+1][4][DHN];
__device__ int   g_flag[NGRP][NPEER];
__device__ float g_sig[(size_t)BN*DHN*TN];     // sigma(x_new) for rnn_out
__device__ float g_part[4][BN][TN];

__device__ __forceinline__ float sigmoidf_(float x){ return 1.0f/(1.0f + __expf(-x)); }

__device__ __forceinline__ unsigned long long pack2(float lo, float hi){
    unsigned long long r; asm("mov.b64 %0, {%1,%2};" : "=l"(r) : "f"(lo), "f"(hi)); return r;
}
__device__ __forceinline__ void unpack2(unsigned long long v, float &lo, float &hi){
    asm("mov.b64 {%0,%1}, %2;" : "=f"(lo), "=f"(hi) : "l"(v));
}
__device__ __forceinline__ void fma2(unsigned long long &acc, unsigned long long a, unsigned long long b){
    asm("fma.rn.f32x2 %0, %1, %2, %3;" : "=l"(acc) : "l"(a), "l"(b), "l"(acc));
}
__device__ __forceinline__ int ld_acq(const int* p){
    int v; asm volatile("ld.global.acquire.gpu.b32 %0, [%1];" : "=r"(v) : "l"(p) : "memory");
    return v;
}
__device__ __forceinline__ void st_rel(int* p, int v){
    asm volatile("st.global.release.gpu.b32 [%0], %1;" :: "l"(p), "r"(v) : "memory");
}

__global__ void reset_flags(){
    int i = threadIdx.x;
    if (i < NGRP*NPEER) ((int*)g_flag)[i] = -1;
}

// 128 independent CTAs (16 groups x 8 ranks), 512 threads.
// CTA (grp, rank): h-rows [rank*64, rank*64+64) for batches [4*grp, 4*grp+4).
// Thread tid = h_local*8 + dg owns W[hg, :] d-slice [p*64+dg*8, +8) per chunk p.
// Chunk order per CTA: p = (rank+k)&7; k=0 (own) W in smem, k=1..7 W in regs.
__global__ void __launch_bounds__(512,1)
rnn_main(const float* __restrict__ u, const float* __restrict__ r0,
         const float* __restrict__ noise, const float* __restrict__ win,
         const float* __restrict__ w_raw, const float* __restrict__ taus,
         float* __restrict__ xs)
{
    __shared__ float u_sh[4*TN];                       // 16 KB
    __shared__ __align__(16) float own[2][4][72];      // own r chunk, double-buffered
    __shared__ __align__(16) float Wown[512*12];       // own-chunk W, 8 data + 4 pad / thread

    const int tid = threadIdx.x;
    const int h_local = tid >> 3;
    const int dg = tid & 7;
    const int grp  = blockIdx.x >> 3;
    const int rank = blockIdx.x & 7;
    const int hg = rank*64 + h_local;
    const int bbase = grp*4;

    // u (B,T) for this group's 4 batches -> smem (contiguous)
    for (int i = tid; i < 4*TN; i += 512)
        u_sh[i] = u[(size_t)bbase*TN + i];

    // ---- W = |_w| (m is diag(+-1)); own chunk to smem, peers to regs ----
    unsigned long long w2[28];
    {
        const float* wr = w_raw + (size_t)hg*DHN;
        {
            int d0 = rank*64 + dg*8;
            #pragma unroll
            for (int j = 0; j < 8; j++)
                Wown[tid*12 + j] = fabsf(wr[d0 + j]);
        }
        #pragma unroll
        for (int k = 1; k < 8; k++){
            int d0 = ((rank + k) & 7)*64 + dg*8;
            #pragma unroll
            for (int j = 0; j < 4; j++)
                w2[(k-1)*4+j] = pack2(fabsf(wr[d0+2*j]), fabsf(wr[d0+2*j+1]));
        }
    }
    const float a_h   = 1.0f/taus[hg];
    const float win_h = win[hg];

    const int b  = dg & 3;            // epilogue lane (dg<4) owns batch b
    const int bg = bbase + b;
    float s = 0.0f;

    // ---- prologue: r_0 = sigmoid(r0) into ring slot 0 + own smem buf 0 ----
    if (dg < 4){
        s = r0[(size_t)bg*DHN + hg];
        float rv = sigmoidf_(s);
        g_ring[grp][0][b][hg] = rv;
        own[0][b][h_local + ((h_local>>3)&4)] = rv;
    }
    __syncthreads();
    if (tid == 0) st_rel(&g_flag[grp][rank], 0);

    // peer ring pointers (slot 0) and flag offsets
    const float* pk[8];
    int off[8];
    #pragma unroll
    for (int k = 1; k < 8; k++){
        int p = (rank + k) & 7;
        pk[k]  = &g_ring[grp][0][0][p*64 + dg*8];
        off[k] = p;
    }
    const int* flb = g_flag[grp];

    float* ring_w = &g_ring[grp][1][b][hg];
    const float* np = noise + (size_t)bg*DHN + hg;
    float* xp = xs    + ((size_t)bg*DHN + hg)*TN;
    float* sp = g_sig + ((size_t)bg*DHN + hg)*TN;

    for (int t = 0; t < TN; t++){
        // prefetch per-step inputs and all peer flags
        float nv = 0.f, uv = 0.f;
        if (dg < 4){ nv = np[0]; uv = u_sh[b*TN + t]; }
        int f[8];
        #pragma unroll
        for (int k = 1; k < 8; k++) f[k] = ld_acq(flb + off[k]);

        unsigned long long acc[4] = {0ull,0ull,0ull,0ull};

        // chunk 0 (own) from smem — overlaps flag latency
        {
            const float* ob = &own[t & 1][0][dg*8 + (dg&4)];
            const ulonglong2* wp = (const ulonglong2*)&Wown[tid*12];
            ulonglong2 wv0 = wp[0];
            ulonglong2 wv1 = wp[1];
            #pragma unroll
            for (int bb = 0; bb < 4; bb++){
                ulonglong2 r1 = *(const ulonglong2*)(ob + bb*72);
                ulonglong2 r2 = *(const ulonglong2*)(ob + bb*72 + 4);
                fma2(acc[bb], wv0.x, r1.x); fma2(acc[bb], wv0.y, r1.y);
                fma2(acc[bb], wv1.x, r2.x); fma2(acc[bb], wv1.y, r2.y);
            }
        }

        // wait for all peers (usually already satisfied by prefetch)
        #pragma unroll
        for (int k = 1; k < 8; k++)
            while (f[k] < t) f[k] = ld_acq(flb + off[k]);

        // chunks 1..7 from L2/L1 (never-reused addresses -> cacheable)
        #pragma unroll
        for (int k = 1; k < 8; k++){
            const float* rp = pk[k];
            #pragma unroll
            for (int bb = 0; bb < 4; bb++){
                ulonglong2 r1 = *(const ulonglong2*)(rp + bb*DHN);
                ulonglong2 r2 = *(const ulonglong2*)(rp + bb*DHN + 4);
                fma2(acc[bb], w2[(k-1)*4+0], r1.x); fma2(acc[bb], w2[(k-1)*4+1], r1.y);
                fma2(acc[bb], w2[(k-1)*4+2], r2.x); fma2(acc[bb], w2[(k-1)*4+3], r2.y);
            }
            pk[k] += 4*DHN;   // advance one slot (2048 floats)
        }

        // reduce across 8 dg lanes
        float sum[4];
        #pragma unroll
        for (int bb = 0; bb < 4; bb++){
            float lo, hi; unpack2(acc[bb], lo, hi); sum[bb] = lo + hi;
        }
        #pragma unroll
        for (int bb = 0; bb < 4; bb++){
            sum[bb] += __shfl_xor_sync(0xffffffffu, sum[bb], 1);
            sum[bb] += __shfl_xor_sync(0xffffffffu, sum[bb], 2);
            sum[bb] += __shfl_xor_sync(0xffffffffu, sum[bb], 4);
        }

        // epilogue
        if (dg < 4){
            float xn = (1.0f - a_h)*s + a_h*sum[b] + win_h*uv + 0.1f*nv;
            s = sigmoidf_(xn);               // sigma(x_new): next x_in + rnn_out input
            float rv = sigmoidf_(s);         // next r
            ring_w[0] = rv;                  // publish to peers (slot t+1)
            own[(t & 1) ^ 1][b][h_local + ((h_local>>3)&4)] = rv;
            xp[t] = xn;
            sp[t] = s;
            ring_w += 4*DHN;
        }
        np += (size_t)BN*DHN;

        __syncthreads();                      // all slices stored (+ STS drained)
        if (tid == 0) st_rel(&g_flag[grp][rank], t + 1);   // cumulative release
    }
}

// Partial dot products over 128-h chunks: pure DRAM streaming, zero MUFU.
__global__ void __launch_bounds__(256)
rnn_out_part(const float* __restrict__ wout)
{
    const int b  = blockIdx.x >> 2;
    const int hc = blockIdx.x & 3;
    __shared__ float wsh[128];
    if (threadIdx.x < 128) wsh[threadIdx.x] = wout[hc*128 + threadIdx.x];
    __syncthreads();

    const float4* base = (const float4*)(g_sig + ((size_t)b*DHN + hc*128)*TN);
    float a0=0.f, a1=0.f, a2=0.f, a3=0.f;
    #pragma unroll 4
    for (int h = 0; h < 128; h++){
        float wv = wsh[h];
        float4 v = base[(size_t)h*(TN/4) + threadIdx.x];
        a0 = fmaf(wv, v.x, a0);
        a1 = fmaf(wv, v.y, a1);
        a2 = fmaf(wv, v.z, a2);
        a3 = fmaf(wv, v.w, a3);
    }
    float4 o; o.x=a0; o.y=a1; o.z=a2; o.w=a3;
    ((float4*)g_part[hc][b])[threadIdx.x] = o;
}

__global__ void __launch_bounds__(256)
rnn_combine(const float* __restrict__ bias, float* __restrict__ out)
{
    const int b = blockIdx.x;
    float4 p0 = ((const float4*)g_part[0][b])[threadIdx.x];
    float4 p1 = ((const float4*)g_part[1][b])[threadIdx.x];
    float4 p2 = ((const float4*)g_part[2][b])[threadIdx.x];
    float4 p3 = ((const float4*)g_part[3][b])[threadIdx.x];
    float bz = bias[0];
    float4 o;
    o.x = (p0.x+p1.x)+(p2.x+p3.x)+bz;
    o.y = (p0.y+p1.y)+(p2.y+p3.y)+bz;
    o.z = (p0.z+p1.z)+(p2.z+p3.z)+bz;
    o.w = (p0.w+p1.w)+(p2.w+p3.w)+bz;
    ((float4*)(out + (size_t)b*TN))[threadIdx.x] = o;
}

extern "C" void kernel_launch(void* const* d_in, const int* in_sizes, int n_in,
                              void* d_out, int out_size)
{
    // metadata order: u, r0, noise, win, m, wout, _w, taus, bias
    const float* u     = (const float*)d_in[0];
    const float* r0    = (const float*)d_in[1];
    const float* noise = (const float*)d_in[2];
    const float* win   = (const float*)d_in[3];
    const float* wout  = (const float*)d_in[5];
    const float* w_raw = (const float*)d_in[6];
    const float* taus  = (const float*)d_in[7];
    const float* bias  = (const float*)d_in[8];

    float* out = (float*)d_out;                 // outputs (B, T, 1)
    float* xs  = out + (size_t)BN * TN;         // xs (B, DH, T)

    reset_flags<<<1, 128>>>();
    rnn_main<<<NGRP*NPEER, 512>>>(u, r0, noise, win, w_raw, taus, xs);
    rnn_out_part<<<BN*4, 256>>>(wout);
    rnn_combine<<<BN, 256>>>(bias, out);
}

// round 9
// speedup vs baseline: 7.2389x; 7.2389x over previous
#include <cuda_runtime.h>
#include <cstdint>

#define DHN 512
#define BN  64
#define TN  1024
#define NRANK 4          // CTAs per cluster
#define DSL 128          // d/h slice per rank
#define NB  2            // batches per cluster
#define WROW 68          // padded W smem row (64 data + 4 pad)

// dynamic smem layout (floats)
#define OFF_W    0
#define OFF_U    (512*WROW)                  // 34816
#define OFF_R    (OFF_U + NB*TN)             // +2048
#define OFF_P    (OFF_R + 2*NB*DSL)          // +512
#define OFF_SX   (OFF_P + 2*NRANK*NB*DSL)    // +2048
#define OFF_SS   (OFF_SX + 16*NB*DSL)        // +4096
#define SMEM_FLOATS (OFF_SS + 16*NB*DSL)
#define SMEM_BYTES (SMEM_FLOATS*4)

__device__ float g_sig[(size_t)BN*DHN*TN];   // sigma(x_new) for rnn_out
__device__ float g_part[8][BN][TN];

__device__ __forceinline__ float sigmoidf_(float x){ return 1.0f/(1.0f + __expf(-x)); }

__device__ __forceinline__ unsigned long long pack2(float lo, float hi){
    unsigned long long r; asm("mov.b64 %0, {%1,%2};" : "=l"(r) : "f"(lo), "f"(hi)); return r;
}
__device__ __forceinline__ void unpack2(unsigned long long v, float &lo, float &hi){
    asm("mov.b64 {%0,%1}, %2;" : "=f"(lo), "=f"(hi) : "l"(v));
}
__device__ __forceinline__ void fma2(unsigned long long &acc, unsigned long long a, unsigned long long b){
    asm("fma.rn.f32x2 %0, %1, %2, %3;" : "=l"(acc) : "l"(a), "l"(b), "l"(acc));
}
__device__ __forceinline__ uint32_t smem_u32(const void* p){
    uint32_t a; asm("{ .reg .u64 t; cvta.to.shared.u64 t, %1; cvt.u32.u64 %0, t; }" : "=r"(a) : "l"(p)); return a;
}
__device__ __forceinline__ uint32_t mapa_(uint32_t addr, uint32_t rank){
    uint32_t r; asm("mapa.shared::cluster.u32 %0, %1, %2;" : "=r"(r) : "r"(addr), "r"(rank)); return r;
}
__device__ __forceinline__ void st_cluster_f32(uint32_t addr, float v){
    asm volatile("st.shared::cluster.f32 [%0], %1;" :: "r"(addr), "f"(v) : "memory");
}
__device__ __forceinline__ void cluster_sync_(){
    asm volatile("barrier.cluster.arrive.aligned;" ::: "memory");
    asm volatile("barrier.cluster.wait.aligned;" ::: "memory");
}
__device__ __forceinline__ uint32_t ctarank_(){
    uint32_t r; asm("mov.u32 %0, %%cluster_ctarank;" : "=r"(r)); return r;
}

// 32 clusters x 4 CTAs x 512 threads.
// Cluster c: batches {2c, 2c+1}. Rank k: d-slice AND h-slice [128k, 128k+128).
// Thread tid = global h row; computes partial_b[h] = sum_{d in slice} W[h,d]*r_b[d]
// entirely in-thread (64 d in regs, 64 d in smem), then ships the 2 partials to
// the rank owning h. Epilogue for own h-slice; r never leaves the producing CTA.
__global__ void __cluster_dims__(NRANK,1,1) __launch_bounds__(512,1)
rnn_main(const float* __restrict__ u, const float* __restrict__ r0,
         const float* __restrict__ noise, const float* __restrict__ win,
         const float* __restrict__ w_raw, const float* __restrict__ taus,
         float* __restrict__ xs)
{
    extern __shared__ __align__(16) float sm[];
    float* W_sh   = sm + OFF_W;      // [512][WROW]
    float* u_sh   = sm + OFF_U;      // [NB][TN]
    float* r_own  = sm + OFF_R;      // [2 buf][NB][DSL]
    float* p_sh   = sm + OFF_P;      // [2 buf][NRANK src][NB][DSL]
    float* stg_x  = sm + OFF_SX;     // [16 t][NB][DSL]
    float* stg_s  = sm + OFF_SS;     // [16 t][NB][DSL]

    const int tid   = threadIdx.x;            // == global h row
    const uint32_t rank = ctarank_();
    const int cid   = blockIdx.x / NRANK;
    const int bbase = cid * NB;

    // u slices for this cluster's 2 batches
    for (int i = tid; i < NB*TN; i += 512)
        u_sh[i] = u[(size_t)bbase*TN + i];

    // ---- W row: |_w| (m is diag(+-1)); d 0..63 regs, d 64..127 smem ----
    unsigned long long w2[32];
    {
        const float* wr = w_raw + (size_t)tid*DHN + (int)rank*DSL;
        #pragma unroll
        for (int k = 0; k < 32; k++)
            w2[k] = pack2(fabsf(wr[2*k]), fabsf(wr[2*k+1]));
        float* wsm = W_sh + tid*WROW;
        #pragma unroll
        for (int j = 0; j < 64; j++)
            wsm[j] = fabsf(wr[64 + j]);
    }

    // epilogue thread (tid<256): b = tid>>7, hl = tid&127, hg = rank*128+hl
    const int eb  = tid >> 7;
    const int ehl = tid & 127;
    const int ehg = (int)rank*DSL + ehl;
    const int ebg = bbase + eb;
    float a_h = 0.f, win_h = 0.f, s = 0.f;
    if (tid < 256){
        a_h   = 1.0f/taus[ehg];
        win_h = win[ehg];
        s     = r0[(size_t)ebg*DHN + ehg];
        float rv = sigmoidf_(s);
        r_own[(0*NB + eb)*DSL + ehl] = rv;    // buf 0
    }

    // delivery targets: partials for h=tid go to rank j = tid>>7
    const uint32_t dj  = (uint32_t)(tid >> 7);
    const int      dhl = tid & 127;
    const uint32_t pdst0 = mapa_(smem_u32(&p_sh[((0*NRANK + (int)rank)*NB + 0)*DSL + dhl]), dj);
    const uint32_t pdst1 = mapa_(smem_u32(&p_sh[((1*NRANK + (int)rank)*NB + 0)*DSL + dhl]), dj);

    __syncthreads();   // r_own[0], W_sh, u_sh ready (matvec0 reads own smem only)

    const float* np = noise + (size_t)ebg*DHN + ehg;   // + t*BN*DHN per step

    for (int t = 0; t < TN; t++){
        const int buf = t & 1;

        // prefetch noise for epilogue (used after the barrier)
        float nv = 0.f;
        if (tid < 256) nv = np[(size_t)t*BN*DHN];

        // ---- matvec: full 128-d dot for h=tid, both batches ----
        unsigned long long a00=0ull, a01=0ull, a10=0ull, a11=0ull;
        const ulonglong2* rp0 = (const ulonglong2*)(r_own + (buf*NB + 0)*DSL);
        const ulonglong2* rp1 = (const ulonglong2*)(r_own + (buf*NB + 1)*DSL);
        #pragma unroll
        for (int k = 0; k < 16; k++){
            ulonglong2 v0 = rp0[k], v1 = rp1[k];
            fma2(a00, w2[2*k],   v0.x); fma2(a01, w2[2*k+1], v0.y);
            fma2(a10, w2[2*k],   v1.x); fma2(a11, w2[2*k+1], v1.y);
        }
        {
            const ulonglong2* wp = (const ulonglong2*)(W_sh + tid*WROW);
            #pragma unroll
            for (int k = 0; k < 16; k++){
                ulonglong2 wv = wp[k];
                ulonglong2 v0 = rp0[16+k], v1 = rp1[16+k];
                fma2(a00, wv.x, v0.x); fma2(a01, wv.y, v0.y);
                fma2(a10, wv.x, v1.x); fma2(a11, wv.y, v1.y);
            }
        }
        float pb0, pb1;
        { float l0,h0,l1,h1; unpack2(a00,l0,h0); unpack2(a01,l1,h1); pb0 = (l0+h0)+(l1+h1); }
        { float l0,h0,l1,h1; unpack2(a10,l0,h0); unpack2(a11,l1,h1); pb1 = (l0+h0)+(l1+h1); }

        // ---- ship partials to the h-owning rank (3/4 remote, 1/4 self) ----
        const uint32_t pd = buf ? pdst1 : pdst0;
        st_cluster_f32(pd,            pb0);
        st_cluster_f32(pd + DSL*4,    pb1);

        cluster_sync_();   // partials visible cluster-wide

        // ---- reduce + epilogue for own h-slice ----
        if (tid < 256){
            const float* pb = p_sh + buf*NRANK*NB*DSL + eb*DSL + ehl;
            float dot = (pb[0] + pb[NB*DSL]) + (pb[2*NB*DSL] + pb[3*NB*DSL]);
            float xn = (1.0f - a_h)*s + a_h*dot + win_h*u_sh[eb*TN + t] + 0.1f*nv;
            stg_x[((t&15)*NB + eb)*DSL + ehl] = xn;
            s = sigmoidf_(xn);
            stg_s[((t&15)*NB + eb)*DSL + ehl] = s;
            r_own[(((t+1)&1)*NB + eb)*DSL + ehl] = sigmoidf_(s);   // next r, local only
        }
        __syncthreads();

        // ---- coalesced flush of staged xs/sigma every 16 steps ----
        if ((t & 15) == 15){
            const int t0 = t - 15;
            #pragma unroll
            for (int it = 0; it < 2; it++){
                int idx = tid + it*512;            // 1024 quads
                int q  = idx & 3;
                int hl = idx >> 2 & 127;
                int b  = idx >> 9;
                float4 vx, vs;
                vx.x = stg_x[(((4*q+0)*NB)+b)*DSL + hl];
                vx.y = stg_x[(((4*q+1)*NB)+b)*DSL + hl];
                vx.z = stg_x[(((4*q+2)*NB)+b)*DSL + hl];
                vx.w = stg_x[(((4*q+3)*NB)+b)*DSL + hl];
                vs.x = stg_s[(((4*q+0)*NB)+b)*DSL + hl];
                vs.y = stg_s[(((4*q+1)*NB)+b)*DSL + hl];
                vs.z = stg_s[(((4*q+2)*NB)+b)*DSL + hl];
                vs.w = stg_s[(((4*q+3)*NB)+b)*DSL + hl];
                size_t row = ((size_t)(bbase+b)*DHN + (int)rank*DSL + hl)*TN + t0 + 4*q;
                *(float4*)(xs    + row) = vx;
                *(float4*)(g_sig + row) = vs;
            }
            // no extra sync: next epilogue write to stg happens only after the
            // next cluster_sync_, which all flushing threads must reach first.
        }
    }
    cluster_sync_();
}

// Partial dot products over 64-h chunks: pure DRAM streaming, zero MUFU.
__global__ void __launch_bounds__(256)
rnn_out_part(const float* __restrict__ wout)
{
    const int b  = blockIdx.x >> 3;
    const int hc = blockIdx.x & 7;
    __shared__ float wsh[64];
    if (threadIdx.x < 64) wsh[threadIdx.x] = wout[hc*64 + threadIdx.x];
    __syncthreads();

    const float4* base = (const float4*)(g_sig + ((size_t)b*DHN + hc*64)*TN);
    float a0=0.f, a1=0.f, a2=0.f, a3=0.f;
    #pragma unroll 4
    for (int h = 0; h < 64; h++){
        float wv = wsh[h];
        float4 v = base[(size_t)h*(TN/4) + threadIdx.x];
        a0 = fmaf(wv, v.x, a0);
        a1 = fmaf(wv, v.y, a1);
        a2 = fmaf(wv, v.z, a2);
        a3 = fmaf(wv, v.w, a3);
    }
    float4 o; o.x=a0; o.y=a1; o.z=a2; o.w=a3;
    ((float4*)g_part[hc][b])[threadIdx.x] = o;
}

__global__ void __launch_bounds__(256)
rnn_combine(const float* __restrict__ bias, float* __restrict__ out)
{
    const int b = blockIdx.x;
    float4 acc = {0.f,0.f,0.f,0.f};
    #pragma unroll
    for (int c = 0; c < 8; c++){
        float4 p = ((const float4*)g_part[c][b])[threadIdx.x];
        acc.x += p.x; acc.y += p.y; acc.z += p.z; acc.w += p.w;
    }
    float bz = bias[0];
    acc.x += bz; acc.y += bz; acc.z += bz; acc.w += bz;
    ((float4*)(out + (size_t)b*TN))[threadIdx.x] = acc;
}

extern "C" void kernel_launch(void* const* d_in, const int* in_sizes, int n_in,
                              void* d_out, int out_size)
{
    // metadata order: u, r0, noise, win, m, wout, _w, taus, bias
    const float* u     = (const float*)d_in[0];
    const float* r0    = (const float*)d_in[1];
    const float* noise = (const float*)d_in[2];
    const float* win   = (const float*)d_in[3];
    const float* wout  = (const float*)d_in[5];
    const float* w_raw = (const float*)d_in[6];
    const float* taus  = (const float*)d_in[7];
    const float* bias  = (const float*)d_in[8];

    float* out = (float*)d_out;                 // outputs (B, T, 1)
    float* xs  = out + (size_t)BN * TN;         // xs (B, DH, T)

    static int inited = 0;
    if (!inited){
        cudaFuncSetAttribute(rnn_main, cudaFuncAttributeMaxDynamicSharedMemorySize, SMEM_BYTES);
        inited = 1;
    }

    rnn_main<<<32*NRANK, 512, SMEM_BYTES>>>(u, r0, noise, win, w_raw, taus, xs);
    rnn_out_part<<<BN*8, 256>>>(wout);
    rnn_combine<<<BN, 256>>>(bias, out);
}

// round 10
// speedup vs baseline: 7.8286x; 1.0815x over previous
#include <cuda_runtime.h>
#include <cstdint>

#define DHN 512
#define BN  64
#define TN  1024
#define NRANK 4          // CTAs per cluster
#define DSL 128          // d/h slice per rank
#define NB  2            // batches per cluster
#define WU32 36          // padded bf16-W smem row in u32 (32 data + 4 pad)

// dynamic smem layout (float-sized units)
#define OFF_WB   0
#define OFF_U    (512*WU32)                  // 18432
#define OFF_R    (OFF_U + NB*TN)             // +2048
#define OFF_P    (OFF_R + 2*NB*DSL)          // +512
#define OFF_SX   (OFF_P + 2*NRANK*NB*DSL)    // +2048
#define OFF_SS   (OFF_SX + 16*NB*DSL)        // +4096
#define SMEM_FLOATS (OFF_SS + 16*NB*DSL)
#define SMEM_BYTES (SMEM_FLOATS*4)

__device__ float g_sig[(size_t)BN*DHN*TN];   // sigma(x_new) for rnn_out
__device__ float g_part[8][BN][TN];

__device__ __forceinline__ float sigmoidf_(float x){ return 1.0f/(1.0f + __expf(-x)); }

__device__ __forceinline__ unsigned long long pack2(float lo, float hi){
    unsigned long long r; asm("mov.b64 %0, {%1,%2};" : "=l"(r) : "f"(lo), "f"(hi)); return r;
}
__device__ __forceinline__ void unpack2(unsigned long long v, float &lo, float &hi){
    asm("mov.b64 {%0,%1}, %2;" : "=f"(lo), "=f"(hi) : "l"(v));
}
__device__ __forceinline__ void fma2(unsigned long long &acc, unsigned long long a, unsigned long long b){
    asm("fma.rn.f32x2 %0, %1, %2, %3;" : "=l"(acc) : "l"(a), "l"(b), "l"(acc));
}
// bf16x2 word -> packed f32x2: fp32(bf16) is just bf16<<16
__device__ __forceinline__ unsigned long long bf2f2(uint32_t v){
    uint32_t lo, hi; unsigned long long r;
    asm("shl.b32 %0, %1, 16;"          : "=r"(lo) : "r"(v));
    asm("and.b32 %0, %1, 0xffff0000;"  : "=r"(hi) : "r"(v));
    asm("mov.b64 %0, {%1,%2};" : "=l"(r) : "r"(lo), "r"(hi));
    return r;
}
__device__ __forceinline__ uint32_t f2bf2(float lo, float hi){
    uint32_t r;
    asm("cvt.rn.bf16x2.f32 %0, %1, %2;" : "=r"(r) : "f"(hi), "f"(lo)); // first src -> high half
    return r;
}
__device__ __forceinline__ uint32_t smem_u32(const void* p){
    uint32_t a; asm("{ .reg .u64 t; cvta.to.shared.u64 t, %1; cvt.u32.u64 %0, t; }" : "=r"(a) : "l"(p)); return a;
}
__device__ __forceinline__ uint32_t mapa_(uint32_t addr, uint32_t rank){
    uint32_t r; asm("mapa.shared::cluster.u32 %0, %1, %2;" : "=r"(r) : "r"(addr), "r"(rank)); return r;
}
__device__ __forceinline__ void st_cluster_f32(uint32_t addr, float v){
    asm volatile("st.shared::cluster.f32 [%0], %1;" :: "r"(addr), "f"(v) : "memory");
}
__device__ __forceinline__ void cluster_arrive_(){
    asm volatile("barrier.cluster.arrive.aligned;" ::: "memory");
}
__device__ __forceinline__ void cluster_wait_(){
    asm volatile("barrier.cluster.wait.aligned;" ::: "memory");
}
__device__ __forceinline__ uint32_t ctarank_(){
    uint32_t r; asm("mov.u32 %0, %%cluster_ctarank;" : "=r"(r)); return r;
}

// 32 clusters x 4 CTAs x 512 threads.
// Cluster c: batches {2c, 2c+1}. Rank k: d-slice AND h-slice [128k, 128k+128).
// Thread tid = global h row: full 128-d partial dot in-thread.
//   d 0..63  : fp32 in 32 f32x2 registers
//   d 64..127: bf16x2 in a pad-36 smem row (expanded on the fly, SHL/AND)
// Partials shipped to the h-owning rank; r never leaves the producing CTA.
__global__ void __cluster_dims__(NRANK,1,1) __launch_bounds__(512,1)
rnn_main(const float* __restrict__ u, const float* __restrict__ r0,
         const float* __restrict__ noise, const float* __restrict__ win,
         const float* __restrict__ w_raw, const float* __restrict__ taus,
         float* __restrict__ xs)
{
    extern __shared__ __align__(16) float sm[];
    uint32_t* W_bh = (uint32_t*)(sm + OFF_WB);   // [512][WU32] bf16x2 words
    float* u_sh   = sm + OFF_U;      // [NB][TN]
    float* r_own  = sm + OFF_R;      // [2 buf][NB][DSL]
    float* p_sh   = sm + OFF_P;      // [2 buf][NRANK src][NB][DSL]
    float* stg_x  = sm + OFF_SX;     // [16 t][NB][DSL]
    float* stg_s  = sm + OFF_SS;     // [16 t][NB][DSL]

    const int tid   = threadIdx.x;            // == global h row
    const uint32_t rank = ctarank_();
    const int cid   = blockIdx.x / NRANK;
    const int bbase = cid * NB;

    // u slices for this cluster's 2 batches
    for (int i = tid; i < NB*TN; i += 512)
        u_sh[i] = u[(size_t)bbase*TN + i];

    // ---- W row: |_w| (m is diag(+-1)); d 0..63 regs fp32, d 64..127 smem bf16 ----
    unsigned long long w2[32];
    {
        const float* wr = w_raw + (size_t)tid*DHN + (int)rank*DSL;
        #pragma unroll
        for (int k = 0; k < 32; k++)
            w2[k] = pack2(fabsf(wr[2*k]), fabsf(wr[2*k+1]));
        uint32_t* wb = W_bh + tid*WU32;
        #pragma unroll
        for (int j = 0; j < 32; j++)
            wb[j] = f2bf2(fabsf(wr[64 + 2*j]), fabsf(wr[64 + 2*j + 1]));
    }

    // epilogue thread (tid<256): b = tid>>7, hl = tid&127, hg = rank*128+hl
    const int eb  = tid >> 7;
    const int ehl = tid & 127;
    const int ehg = (int)rank*DSL + ehl;
    const int ebg = bbase + eb;
    float a_h = 0.f, win_h = 0.f, s = 0.f;
    if (tid < 256){
        a_h   = 1.0f/taus[ehg];
        win_h = win[ehg];
        s     = r0[(size_t)ebg*DHN + ehg];
        r_own[(0*NB + eb)*DSL + ehl] = sigmoidf_(s);    // buf 0
    }

    // delivery targets: partials for h=tid go to rank j = tid>>7
    const uint32_t dj  = (uint32_t)(tid >> 7);
    const int      dhl = tid & 127;
    const uint32_t pdst0 = mapa_(smem_u32(&p_sh[((0*NRANK + (int)rank)*NB + 0)*DSL + dhl]), dj);
    const uint32_t pdst1 = mapa_(smem_u32(&p_sh[((1*NRANK + (int)rank)*NB + 0)*DSL + dhl]), dj);

    __syncthreads();   // r_own[0], W_bh, u_sh ready

    const float* np = noise + (size_t)ebg*DHN + ehg;   // + t*BN*DHN per step

    for (int t = 0; t < TN; t++){
        const int buf = t & 1;

        // prefetch noise for epilogue (used after the barrier)
        float nv = 0.f;
        if (tid < 256) nv = np[(size_t)t*BN*DHN];

        // ---- matvec: full 128-d dot for h=tid, both batches ----
        unsigned long long a00=0ull, a01=0ull, a10=0ull, a11=0ull;
        const ulonglong2* rp0 = (const ulonglong2*)(r_own + (buf*NB + 0)*DSL);
        const ulonglong2* rp1 = (const ulonglong2*)(r_own + (buf*NB + 1)*DSL);
        #pragma unroll
        for (int k = 0; k < 16; k++){
            ulonglong2 v0 = rp0[k], v1 = rp1[k];
            fma2(a00, w2[2*k],   v0.x); fma2(a01, w2[2*k+1], v0.y);
            fma2(a10, w2[2*k],   v1.x); fma2(a11, w2[2*k+1], v1.y);
        }
        {
            const uint32_t* wp = W_bh + tid*WU32;
            #pragma unroll
            for (int k = 0; k < 8; k++){
                uint4 wv = *(const uint4*)(wp + 4*k);   // d = 64+8k .. 71+8k
                unsigned long long w0 = bf2f2(wv.x), w1 = bf2f2(wv.y);
                unsigned long long w2_ = bf2f2(wv.z), w3 = bf2f2(wv.w);
                ulonglong2 v0a = rp0[16+2*k], v0b = rp0[17+2*k];
                ulonglong2 v1a = rp1[16+2*k], v1b = rp1[17+2*k];
                fma2(a00, w0, v0a.x); fma2(a01, w1, v0a.y);
                fma2(a00, w2_, v0b.x); fma2(a01, w3, v0b.y);
                fma2(a10, w0, v1a.x); fma2(a11, w1, v1a.y);
                fma2(a10, w2_, v1b.x); fma2(a11, w3, v1b.y);
            }
        }
        float pb0, pb1;
        { float l0,h0,l1,h1; unpack2(a00,l0,h0); unpack2(a01,l1,h1); pb0 = (l0+h0)+(l1+h1); }
        { float l0,h0,l1,h1; unpack2(a10,l0,h0); unpack2(a11,l1,h1); pb1 = (l0+h0)+(l1+h1); }

        // ---- ship partials to the h-owning rank (3/4 remote, 1/4 self) ----
        const uint32_t pd = buf ? pdst1 : pdst0;
        st_cluster_f32(pd,         pb0);
        st_cluster_f32(pd + DSL*4, pb1);

        cluster_arrive_();

        // ---- coalesced flush of the PREVIOUS 16-step block, hidden in the
        //      arrive->wait gap (stg slots 0..15 are stable: this step's
        //      epilogue writes only after the wait) ----
        if ((t & 15) == 0 && t){
            const int t0 = t - 16;
            #pragma unroll
            for (int it = 0; it < 2; it++){
                int idx = tid + it*512;            // 1024 quads
                int q  = idx & 3;
                int hl = (idx >> 2) & 127;
                int b  = idx >> 9;
                float4 vx, vs;
                vx.x = stg_x[(((4*q+0)*NB)+b)*DSL + hl];
                vx.y = stg_x[(((4*q+1)*NB)+b)*DSL + hl];
                vx.z = stg_x[(((4*q+2)*NB)+b)*DSL + hl];
                vx.w = stg_x[(((4*q+3)*NB)+b)*DSL + hl];
                vs.x = stg_s[(((4*q+0)*NB)+b)*DSL + hl];
                vs.y = stg_s[(((4*q+1)*NB)+b)*DSL + hl];
                vs.z = stg_s[(((4*q+2)*NB)+b)*DSL + hl];
                vs.w = stg_s[(((4*q+3)*NB)+b)*DSL + hl];
                size_t row = ((size_t)(bbase+b)*DHN + (int)rank*DSL + hl)*TN + t0 + 4*q;
                *(float4*)(xs    + row) = vx;
                *(float4*)(g_sig + row) = vs;
            }
        }

        cluster_wait_();   // partials visible cluster-wide

        // ---- reduce + epilogue for own h-slice ----
        if (tid < 256){
            const float* pb = p_sh + buf*NRANK*NB*DSL + eb*DSL + ehl;
            float dot = (pb[0] + pb[NB*DSL]) + (pb[2*NB*DSL] + pb[3*NB*DSL]);
            float xn = (1.0f - a_h)*s + a_h*dot + win_h*u_sh[eb*TN + t] + 0.1f*nv;
            stg_x[((t&15)*NB + eb)*DSL + ehl] = xn;
            s = sigmoidf_(xn);
            stg_s[((t&15)*NB + eb)*DSL + ehl] = s;
            r_own[(((t+1)&1)*NB + eb)*DSL + ehl] = sigmoidf_(s);   // next r, local only
        }
        __syncthreads();
    }

    // final block flush (t = 1008..1023)
    {
        const int t0 = TN - 16;
        #pragma unroll
        for (int it = 0; it < 2; it++){
            int idx = tid + it*512;
            int q  = idx & 3;
            int hl = (idx >> 2) & 127;
            int b  = idx >> 9;
            float4 vx, vs;
            vx.x = stg_x[(((4*q+0)*NB)+b)*DSL + hl];
            vx.y = stg_x[(((4*q+1)*NB)+b)*DSL + hl];
            vx.z = stg_x[(((4*q+2)*NB)+b)*DSL + hl];
            vx.w = stg_x[(((4*q+3)*NB)+b)*DSL + hl];
            vs.x = stg_s[(((4*q+0)*NB)+b)*DSL + hl];
            vs.y = stg_s[(((4*q+1)*NB)+b)*DSL + hl];
            vs.z = stg_s[(((4*q+2)*NB)+b)*DSL + hl];
            vs.w = stg_s[(((4*q+3)*NB)+b)*DSL + hl];
            size_t row = ((size_t)(bbase+b)*DHN + (int)rank*DSL + hl)*TN + t0 + 4*q;
            *(float4*)(xs    + row) = vx;
            *(float4*)(g_sig + row) = vs;
        }
    }

    cluster_arrive_();   // exit safety: no CTA leaves while peers' remote
    cluster_wait_();     // stores could still be in flight
}

// Partial dot products over 64-h chunks: pure DRAM streaming, zero MUFU.
__global__ void __launch_bounds__(256)
rnn_out_part(const float* __restrict__ wout)
{
    const int b  = blockIdx.x >> 3;
    const int hc = blockIdx.x & 7;
    __shared__ float wsh[64];
    if (threadIdx.x < 64) wsh[threadIdx.x] = wout[hc*64 + threadIdx.x];
    __syncthreads();

    const float4* base = (const float4*)(g_sig + ((size_t)b*DHN + hc*64)*TN);
    float a0=0.f, a1=0.f, a2=0.f, a3=0.f;
    #pragma unroll 4
    for (int h = 0; h < 64; h++){
        float wv = wsh[h];
        float4 v = base[(size_t)h*(TN/4) + threadIdx.x];
        a0 = fmaf(wv, v.x, a0);
        a1 = fmaf(wv, v.y, a1);
        a2 = fmaf(wv, v.z, a2);
        a3 = fmaf(wv, v.w, a3);
    }
    float4 o; o.x=a0; o.y=a1; o.z=a2; o.w=a3;
    ((float4*)g_part[hc][b])[threadIdx.x] = o;
}

__global__ void __launch_bounds__(256)
rnn_combine(const float* __restrict__ bias, float* __restrict__ out)
{
    const int b = blockIdx.x;
    float4 acc = {0.f,0.f,0.f,0.f};
    #pragma unroll
    for (int c = 0; c < 8; c++){
        float4 p = ((const float4*)g_part[c][b])[threadIdx.x];
        acc.x += p.x; acc.y += p.y; acc.z += p.z; acc.w += p.w;
    }
    float bz = bias[0];
    acc.x += bz; acc.y += bz; acc.z += bz; acc.w += bz;
    ((float4*)(out + (size_t)b*TN))[threadIdx.x] = acc;
}

extern "C" void kernel_launch(void* const* d_in, const int* in_sizes, int n_in,
                              void* d_out, int out_size)
{
    // metadata order: u, r0, noise, win, m, wout, _w, taus, bias
    const float* u     = (const float*)d_in[0];
    const float* r0    = (const float*)d_in[1];
    const float* noise = (const float*)d_in[2];
    const float* win   = (const float*)d_in[3];
    const float* wout  = (const float*)d_in[5];
    const float* w_raw = (const float*)d_in[6];
    const float* taus  = (const float*)d_in[7];
    const float* bias  = (const float*)d_in[8];

    float* out = (float*)d_out;                 // outputs (B, T, 1)
    float* xs  = out + (size_t)BN * TN;         // xs (B, DH, T)

    static int inited = 0;
    if (!inited){
        cudaFuncSetAttribute(rnn_main, cudaFuncAttributeMaxDynamicSharedMemorySize, SMEM_BYTES);
        inited = 1;
    }

    rnn_main<<<32*NRANK, 512, SMEM_BYTES>>>(u, r0, noise, win, w_raw, taus, xs);
    rnn_out_part<<<BN*8, 256>>>(wout);
    rnn_combine<<<BN, 256>>>(bias, out);
}